// round 17
// baseline (speedup 1.0000x reference)
#include <cuda_runtime.h>
#include <cstdint>

#define BATCH 16384
#define NEG 5
#define WARPS_PER_BLOCK 8
#define THREADS (WARPS_PER_BLOCK * 32)          // 256
#define EPB (WARPS_PER_BLOCK * 2)               // 16 elements/block (2 per warp)
#define NBLOCKS (BATCH / EPB)                   // 1024

__device__ float g_partials[NBLOCKS];
__device__ unsigned int g_count;                // zero-init; last block resets

__device__ __forceinline__ float logsig(float x) {
    // stable log(sigmoid(x)) = min(x,0) - log1p(exp(-|x|))
    return fminf(x, 0.0f) - log1pf(expf(-fabsf(x)));
}

// 32B-per-lane 256-bit gather chunk, non-coherent, L2 evict_last
// (row set fits L2 across graph replays). 16 lanes cover one 512B row.
__device__ __forceinline__ void ldg256(const float* p, float v[8]) {
    uint32_t r0, r1, r2, r3, r4, r5, r6, r7;
    asm volatile(
        "ld.global.nc.L2::evict_last.v8.b32 {%0,%1,%2,%3,%4,%5,%6,%7}, [%8];"
        : "=r"(r0), "=r"(r1), "=r"(r2), "=r"(r3),
          "=r"(r4), "=r"(r5), "=r"(r6), "=r"(r7)
        : "l"(p));
    v[0] = __uint_as_float(r0); v[1] = __uint_as_float(r1);
    v[2] = __uint_as_float(r2); v[3] = __uint_as_float(r3);
    v[4] = __uint_as_float(r4); v[5] = __uint_as_float(r5);
    v[6] = __uint_as_float(r6); v[7] = __uint_as_float(r7);
}

__global__ void __launch_bounds__(THREADS)
sg_fused(const float* __restrict__ emb,
         const int* __restrict__ centers,
         const int* __restrict__ contexts,
         const int* __restrict__ negs,
         float* __restrict__ out) {
    const int lane = threadIdx.x & 31;
    const int warp = threadIdx.x >> 5;
    const int half = lane >> 4;                  // which element (0/1)
    const int hl   = lane & 15;                  // lane within 16-lane group
    const int b    = blockIdx.x * EPB + warp * 2 + half;

    // Index fetch: lanes 0..6 for element 0, lanes 16..22 for element 1.
    int idx = 0;
    if (hl == 0)      idx = centers[b];
    else if (hl == 1) idx = contexts[b];
    else if (hl < 7)  idx = negs[b * NEG + (hl - 2)];

    // 7 LDG.256 per warp, each covering one 512B row per 16-lane half
    // (lane takes 32B). All issued back-to-back.
    float u[8], v[8], w0[8], w1[8], w2[8], w3[8], w4[8];
    {
        const int hbase = lane & 0x10;           // shfl source base per half
        const float* base0 = emb + (size_t)hl * 8;
        int r;
        r = __shfl_sync(0xffffffffu, idx, hbase + 0);
        ldg256(base0 + (size_t)r * 128, u);
        r = __shfl_sync(0xffffffffu, idx, hbase + 1);
        ldg256(base0 + (size_t)r * 128, v);
        r = __shfl_sync(0xffffffffu, idx, hbase + 2);
        ldg256(base0 + (size_t)r * 128, w0);
        r = __shfl_sync(0xffffffffu, idx, hbase + 3);
        ldg256(base0 + (size_t)r * 128, w1);
        r = __shfl_sync(0xffffffffu, idx, hbase + 4);
        ldg256(base0 + (size_t)r * 128, w2);
        r = __shfl_sync(0xffffffffu, idx, hbase + 5);
        ldg256(base0 + (size_t)r * 128, w3);
        r = __shfl_sync(0xffffffffu, idx, hbase + 6);
        ldg256(base0 + (size_t)r * 128, w4);
    }

    // sum_k (u . nv_k) == u . (sum_k nv_k)
    float pos = 0.0f, neg = 0.0f;
    #pragma unroll
    for (int i = 0; i < 8; i++) {
        float ns = w0[i] + w1[i] + w2[i] + w3[i] + w4[i];
        pos += u[i] * v[i];
        neg += u[i] * ns;
    }

    // Reduce within each 16-lane half (xor 8,4,2,1 stays inside the half).
    #pragma unroll
    for (int o = 8; o > 0; o >>= 1) {
        pos += __shfl_xor_sync(0xffffffffu, pos, o);
        neg += __shfl_xor_sync(0xffffffffu, neg, o);
    }

    __shared__ float sm[EPB];
    __shared__ bool is_last;
    if (hl == 0)
        sm[warp * 2 + half] = logsig(pos) + logsig(-neg);
    __syncthreads();

    if (threadIdx.x == 0) {
        float s = 0.0f;
        #pragma unroll
        for (int i = 0; i < EPB; i++) s += sm[i];
        g_partials[blockIdx.x] = s;
        __threadfence();
        unsigned int t = atomicAdd(&g_count, 1u);
        is_last = (t == NBLOCKS - 1);
    }
    __syncthreads();

    // Last block: deterministic fixed-order reduction of 1024 partials.
    if (is_last) {
        __shared__ float red[THREADS];
        float s = 0.0f;
        #pragma unroll
        for (int i = 0; i < NBLOCKS / THREADS; i++)     // 4 per thread
            s += g_partials[threadIdx.x + i * THREADS];
        red[threadIdx.x] = s;
        __syncthreads();
        #pragma unroll
        for (int o = THREADS / 2; o > 0; o >>= 1) {
            if (threadIdx.x < o) red[threadIdx.x] += red[threadIdx.x + o];
            __syncthreads();
        }
        if (threadIdx.x == 0) {
            out[0] = -red[0];
            g_count = 0;    // reset for next graph replay (determinism)
        }
    }
}

extern "C" void kernel_launch(void* const* d_in, const int* in_sizes, int n_in,
                              void* d_out, int out_size) {
    const float* emb      = (const float*)d_in[0];
    const int*   centers  = (const int*)  d_in[1];
    const int*   contexts = (const int*)  d_in[2];
    const int*   negs     = (const int*)  d_in[3];
    float*       out      = (float*)d_out;

    sg_fused<<<NBLOCKS, THREADS>>>(emb, centers, contexts, negs, out);
}